// round 3
// baseline (speedup 1.0000x reference)
#include <cuda_runtime.h>

#define BB     4
#define SS     2048
#define DD     768
#define NSPAN  4096
#define PW     20          // pos/width embedding dim
#define CS_ROWS (SS + 1)   // 2049
#define CHUNKS  32
#define CHUNK_LEN (SS / CHUNKS)   // 64
#define ROW_F   2364       // output floats per (b,n) row
#define ROW_V4  591        // ROW_F / 4

// ---- scratch (no allocations allowed) ----
__device__ float g_cs[(size_t)BB * CS_ROWS * DD];      // prefix sums, ~24 MB
__device__ float g_chunk[BB * CHUNKS * DD];            // per-chunk sums
__device__ int   g_spans[2 * NSPAN];
__device__ int   g_pt[SS];

__constant__ int c_bins[16] = {0,1,2,3,4,5,7,8,9,10,15,16,31,32,63,64};

// ---------------------------------------------------------------------------
// Kernel 0: dtype-robust index conversion (int64 vs int32 detection).
// If spans arrived as little-endian int64, every odd 32-bit word is the high
// half of a value < 2048 → zero. For int32 random data, 64 consecutive odd
// words all-zero is impossible. Deterministic: same input -> same result.
// ---------------------------------------------------------------------------
__global__ void convert_idx_kernel(const int* __restrict__ spans_raw,
                                   const int* __restrict__ pt_raw) {
    __shared__ int s_is64;
    if (threadIdx.x == 0) {
        int nz = 0;
        #pragma unroll
        for (int i = 1; i < 128; i += 2) nz |= spans_raw[i];
        s_is64 = (nz == 0) ? 1 : 0;
    }
    __syncthreads();
    const int is64 = s_is64;
    int idx = blockIdx.x * blockDim.x + threadIdx.x;
    if (idx < 2 * NSPAN) {
        g_spans[idx] = is64 ? spans_raw[2 * idx] : spans_raw[idx];
    } else if (idx < 2 * NSPAN + SS) {
        int j = idx - 2 * NSPAN;
        g_pt[j] = is64 ? pt_raw[2 * j] : pt_raw[j];
    }
}

// ---------------------------------------------------------------------------
// Kernel 1: per-chunk column sums.  grid = BB*CHUNKS*(DD/256), block = 256.
// ---------------------------------------------------------------------------
__global__ __launch_bounds__(256) void chunk_sums_kernel(const float* __restrict__ x) {
    const int dtiles = DD / 256;                 // 3
    int d = (blockIdx.x % dtiles) * 256 + threadIdx.x;
    int c = (blockIdx.x / dtiles) % CHUNKS;
    int b =  blockIdx.x / dtiles  / CHUNKS;
    const float* xp = x + ((size_t)(b * SS + c * CHUNK_LEN)) * DD + d;
    float acc = 0.f;
    #pragma unroll 8
    for (int s = 0; s < CHUNK_LEN; ++s) acc += xp[(size_t)s * DD];
    g_chunk[(b * CHUNKS + c) * DD + d] = acc;
}

// ---------------------------------------------------------------------------
// Kernel 2: write inclusive prefix sums with cross-chunk offset.
// ---------------------------------------------------------------------------
__global__ __launch_bounds__(256) void prefix_kernel(const float* __restrict__ x) {
    const int dtiles = DD / 256;
    int d = (blockIdx.x % dtiles) * 256 + threadIdx.x;
    int c = (blockIdx.x / dtiles) % CHUNKS;
    int b =  blockIdx.x / dtiles  / CHUNKS;

    float acc = 0.f;
    for (int cc = 0; cc < c; ++cc) acc += g_chunk[(b * CHUNKS + cc) * DD + d];
    if (c == 0) g_cs[(size_t)b * CS_ROWS * DD + d] = 0.f;   // cs row 0 = zeros

    const float* xp = x + ((size_t)(b * SS + c * CHUNK_LEN)) * DD + d;
    float* cp = g_cs + ((size_t)(b * CS_ROWS + c * CHUNK_LEN + 1)) * DD + d;
    #pragma unroll 4
    for (int s = 0; s < CHUNK_LEN; ++s) {
        acc += xp[(size_t)s * DD];
        cp[(size_t)s * DD] = acc;
    }
}

// ---------------------------------------------------------------------------
// Kernel 3: assemble output rows.  One block per (b, n); 591 float4 per row.
// Segments (float4 slots): mean[0,192) xs0[192,384) pos0[384,389)
//                          xs1[389,581) pos1[581,586) wemb[586,591)
// ---------------------------------------------------------------------------
__global__ __launch_bounds__(256) void span_out_kernel(
        const float* __restrict__ x,
        const float* __restrict__ wtab,
        const float* __restrict__ ptab,
        float* __restrict__ out) {
    const int bn = blockIdx.x;
    const int n  = bn & (NSPAN - 1);
    const int b  = bn >> 12;                     // NSPAN = 4096

    const int s0 = g_spans[2 * n];
    const int s1 = g_spans[2 * n + 1];
    const int width = s1 - s0 + 1;
    int em = 0;
    #pragma unroll
    for (int i = 1; i < 16; ++i) if (c_bins[i] <= width) em = i;
    const float inv_w = 1.0f / (float)width;
    const int pt0 = g_pt[s0];
    const int pt1 = g_pt[s1];

    const float4* cs0 = (const float4*)(g_cs + ((size_t)(b * CS_ROWS + s0)) * DD);
    const float4* cs1 = (const float4*)(g_cs + ((size_t)(b * CS_ROWS + s1 + 1)) * DD);
    const float4* x0  = (const float4*)(x + ((size_t)(b * SS + s0)) * DD);
    const float4* x1  = (const float4*)(x + ((size_t)(b * SS + s1)) * DD);
    const float4* p0  = (const float4*)(ptab + pt0 * PW);
    const float4* p1  = (const float4*)(ptab + pt1 * PW);
    const float4* wv  = (const float4*)(wtab + em * PW);
    float4* o = (float4*)(out + (size_t)bn * ROW_F);

    for (int t = threadIdx.x; t < ROW_V4; t += blockDim.x) {
        float4 v;
        if (t < 192) {
            float4 a = cs1[t], c = cs0[t];
            v.x = (a.x - c.x) * inv_w;
            v.y = (a.y - c.y) * inv_w;
            v.z = (a.z - c.z) * inv_w;
            v.w = (a.w - c.w) * inv_w;
        } else if (t < 384) {
            v = x0[t - 192];
        } else if (t < 389) {
            v = p0[t - 384];
        } else if (t < 581) {
            v = x1[t - 389];
        } else if (t < 586) {
            v = p1[t - 581];
        } else {
            v = wv[t - 586];
        }
        o[t] = v;
    }
}

// ---------------------------------------------------------------------------
extern "C" void kernel_launch(void* const* d_in, const int* in_sizes, int n_in,
                              void* d_out, int out_size) {
    const float* x     = (const float*)d_in[0];
    const int*   spans = (const int*)d_in[1];   // raw words; dtype auto-detected
    const int*   pt    = (const int*)d_in[2];
    const float* wtab  = (const float*)d_in[3];
    const float* ptab  = (const float*)d_in[4];
    float* out = (float*)d_out;

    (void)in_sizes; (void)n_in; (void)out_size;

    convert_idx_kernel<<<(2 * NSPAN + SS + 255) / 256, 256>>>(spans, pt);
    chunk_sums_kernel<<<BB * CHUNKS * (DD / 256), 256>>>(x);
    prefix_kernel<<<BB * CHUNKS * (DD / 256), 256>>>(x);
    span_out_kernel<<<BB * NSPAN, 256>>>(x, wtab, ptab, out);
}

// round 7
// speedup vs baseline: 1.2893x; 1.2893x over previous
#include <cuda_runtime.h>

#define BB     4
#define SS     2048
#define DD     768
#define NSPAN  4096
#define PW     20               // pos/width embedding dim (5 float4)
#define CS_ROWS (SS + 1)        // 2049
#define CHUNKS  32
#define CHUNK_LEN (SS / CHUNKS) // 64
#define ROW_F   2364            // output floats per (b,n) row
#define ROW_V4  591             // ROW_F / 4
#define DT      (DD / 256)      // 3 d-tiles per 256-thread block
#define CHUNK_GRID (BB * CHUNKS * DT)   // 384
#define META_GRID  (NSPAN / 256)        // 16

struct __align__(16) Meta {
    int   s0, s1;
    float invw;
    int   p0off;     // pt0 * 5  (float4 row offset into pos_table)
    int   p1off;     // pt1 * 5
    int   woff;      // em  * 5  (float4 row offset into width_table)
    int   pad0, pad1;
};

// ---- scratch (no allocations allowed) ----
__device__ float g_cs[(size_t)BB * CS_ROWS * DD];   // prefix sums, ~24 MB
__device__ float g_chunk[BB * CHUNKS * DD];         // per-chunk sums
__device__ Meta  g_meta[NSPAN];

__constant__ int c_bins[16] = {0,1,2,3,4,5,7,8,9,10,15,16,31,32,63,64};

// ---------------------------------------------------------------------------
// Kernel 1 (fused): per-chunk column sums  +  per-span metadata.
//   blocks [0, CHUNK_GRID)           : chunk sums
//   blocks [CHUNK_GRID, +META_GRID)  : span meta (dtype-robust int64/int32)
// ---------------------------------------------------------------------------
__global__ __launch_bounds__(256) void chunk_meta_kernel(
        const float* __restrict__ x,
        const int*   __restrict__ spans_raw,
        const int*   __restrict__ pt_raw) {
    if (blockIdx.x < CHUNK_GRID) {
        int d = (blockIdx.x % DT) * 256 + threadIdx.x;
        int c = (blockIdx.x / DT) % CHUNKS;
        int b =  blockIdx.x / DT  / CHUNKS;
        const float* xp = x + ((size_t)(b * SS + c * CHUNK_LEN)) * DD + d;
        float acc = 0.f;
        #pragma unroll 8
        for (int s = 0; s < CHUNK_LEN; ++s) acc += xp[(size_t)s * DD];
        g_chunk[(b * CHUNKS + c) * DD + d] = acc;
        return;
    }

    // --- span metadata ---
    // int64 detection: values < 2048, so little-endian int64 has all odd
    // 32-bit words zero across 64 consecutive samples; impossible for random
    // int32 data. Deterministic.
    __shared__ int s_is64;
    if (threadIdx.x == 0) {
        int nz = 0;
        #pragma unroll
        for (int i = 1; i < 128; i += 2) nz |= spans_raw[i];
        s_is64 = (nz == 0) ? 1 : 0;
    }
    __syncthreads();
    const int is64 = s_is64;

    int n = (blockIdx.x - CHUNK_GRID) * 256 + threadIdx.x;   // < NSPAN
    int s0 = spans_raw[is64 ? 4 * n     : 2 * n];
    int s1 = spans_raw[is64 ? 4 * n + 2 : 2 * n + 1];
    int pt0 = pt_raw[is64 ? 2 * s0 : s0];
    int pt1 = pt_raw[is64 ? 2 * s1 : s1];
    int width = s1 - s0 + 1;
    int em = 0;
    #pragma unroll
    for (int i = 1; i < 16; ++i) if (c_bins[i] <= width) em = i;

    Meta m;
    m.s0 = s0; m.s1 = s1;
    m.invw  = 1.0f / (float)width;
    m.p0off = pt0 * (PW / 4);
    m.p1off = pt1 * (PW / 4);
    m.woff  = em  * (PW / 4);
    m.pad0 = 0; m.pad1 = 0;
    g_meta[n] = m;
}

// ---------------------------------------------------------------------------
// Kernel 2: inclusive prefix sums with cross-chunk offset.
// x is L2-hot from kernel 1; DRAM traffic ~= 24 MB of cs writes.
// ---------------------------------------------------------------------------
__global__ __launch_bounds__(256) void prefix_kernel(const float* __restrict__ x) {
    int d = (blockIdx.x % DT) * 256 + threadIdx.x;
    int c = (blockIdx.x / DT) % CHUNKS;
    int b =  blockIdx.x / DT  / CHUNKS;

    float acc = 0.f;
    for (int cc = 0; cc < c; ++cc) acc += g_chunk[(b * CHUNKS + cc) * DD + d];
    if (c == 0) g_cs[(size_t)b * CS_ROWS * DD + d] = 0.f;   // cs row 0 = zeros

    const float* xp = x + ((size_t)(b * SS + c * CHUNK_LEN)) * DD + d;
    float* cp = g_cs + ((size_t)(b * CS_ROWS + c * CHUNK_LEN + 1)) * DD + d;
    #pragma unroll 4
    for (int s = 0; s < CHUNK_LEN; ++s) {
        acc += xp[(size_t)s * DD];
        cp[(size_t)s * DD] = acc;
    }
}

// ---------------------------------------------------------------------------
// Kernel 3: assemble output rows. One block of 192 threads per (b, n).
// Thread t handles exactly mean[t], xs0[t], xs1[t]; threads 0..14 write the
// 15 tail float4 (pos0 / pos1 / width embeddings). No divergence in the body.
// Output stored with __stcs (streaming) to keep x + cs resident in L2.
// float4 slots: mean[0,192) xs0[192,384) pos0[384,389)
//               xs1[389,581) pos1[581,586) wemb[586,591)
// ---------------------------------------------------------------------------
__global__ __launch_bounds__(192) void span_out_kernel(
        const float* __restrict__ x,
        const float* __restrict__ wtab,
        const float* __restrict__ ptab,
        float* __restrict__ out) {
    const int bn = blockIdx.x;
    const int n  = bn & (NSPAN - 1);
    const int b  = bn >> 12;
    const int t  = threadIdx.x;

    const Meta m = g_meta[n];

    const float4* cs0 = (const float4*)g_cs + (size_t)(b * CS_ROWS + m.s0)     * (DD / 4);
    const float4* cs1 = (const float4*)g_cs + (size_t)(b * CS_ROWS + m.s1 + 1) * (DD / 4);
    const float4* x0  = (const float4*)x    + (size_t)(b * SS + m.s0) * (DD / 4);
    const float4* x1  = (const float4*)x    + (size_t)(b * SS + m.s1) * (DD / 4);
    float4* o = (float4*)out + (size_t)bn * ROW_V4;

    // issue all 4 independent 128-bit loads up front (MLP = 4)
    const float4 a = cs1[t];
    const float4 c = cs0[t];
    const float4 u = x0[t];
    const float4 v = x1[t];

    float4 mv;
    mv.x = (a.x - c.x) * m.invw;
    mv.y = (a.y - c.y) * m.invw;
    mv.z = (a.z - c.z) * m.invw;
    mv.w = (a.w - c.w) * m.invw;

    __stcs(o + t,       mv);
    __stcs(o + 192 + t, u);
    __stcs(o + 389 + t, v);

    if (t < 15) {
        float4 e; int dst;
        if (t < 5)       { e = ((const float4*)ptab)[m.p0off + t];      dst = 384 + t; }
        else if (t < 10) { e = ((const float4*)ptab)[m.p1off + t - 5];  dst = 581 + t - 5; }
        else             { e = ((const float4*)wtab)[m.woff  + t - 10]; dst = 586 + t - 10; }
        __stcs(o + dst, e);
    }
}

// ---------------------------------------------------------------------------
extern "C" void kernel_launch(void* const* d_in, const int* in_sizes, int n_in,
                              void* d_out, int out_size) {
    const float* x     = (const float*)d_in[0];
    const int*   spans = (const int*)d_in[1];   // raw words; dtype auto-detected
    const int*   pt    = (const int*)d_in[2];
    const float* wtab  = (const float*)d_in[3];
    const float* ptab  = (const float*)d_in[4];
    float* out = (float*)d_out;

    (void)in_sizes; (void)n_in; (void)out_size;

    chunk_meta_kernel<<<CHUNK_GRID + META_GRID, 256>>>(x, spans, pt);
    prefix_kernel<<<CHUNK_GRID, 256>>>(x);
    span_out_kernel<<<BB * NSPAN, 192>>>(x, wtab, ptab, out);
}